// round 11
// baseline (speedup 1.0000x reference)
#include <cuda_runtime.h>
#include <cuda_bf16.h>
#include <cstdint>

// BezierSurfaceFitter, all-HMMA: stage1 Tt = bv @ K^T and stage2 out = bu @ T
// both on tensor pipe. CTA = (bc, j-half), grid 1536, 8 warps.
// bf16 H/L split everywhere: X·Y ≈ XH·YH + XH·YL + XL·YH (~2^-18 term dropped).

#define NS  256
#define NP  32
#define NBC 768
#define BSTRIDE_U32 20   // 80-byte row stride (bf16x2 words) for ldsm tiles
#define JH  128          // j columns per CTA

// ---- compile-time Bernstein basis ----
static constexpr float to_f32_ftz(double x) {
    return (x < 1.1754943508222875e-38 && x > -1.1754943508222875e-38)
               ? 0.0f : (float)x;
}
static constexpr uint16_t f32_to_bf16(float f) {
    if (f == 0.0f) return 0;
    uint32_t u = __builtin_bit_cast(uint32_t, f);
    return (uint16_t)((u + 0x7FFFu + ((u >> 16) & 1u)) >> 16);
}
static constexpr float bf16_to_f32(uint16_t h) {
    return __builtin_bit_cast(float, (uint32_t)h << 16);
}
static constexpr double bu_val(int i, int p) {
    double tt = ((double)i + 0.5) / NS, u = 1.0 - tt;
    double c = 1.0;
    for (int k = 0; k < p; ++k) c = c * (double)(NP - 1 - k) / (double)(k + 1);
    double tp = 1.0; for (int k = 0; k < p; ++k) tp *= tt;
    double up = 1.0; for (int k = 0; k < NP - 1 - p; ++k) up *= u;
    return c * tp * up;
}
// bf16-pair tables in mma-A-fragment addressing: v[i*16+cp] = (bu[i][2cp], bu[i][2cp+1])
struct ATbl { uint32_t v[NS * 16]; };
static constexpr ATbl make_aH() {
    ATbl t{};
    for (int i = 0; i < NS; ++i)
        for (int cp = 0; cp < 16; ++cp) {
            uint16_t h0 = f32_to_bf16(to_f32_ftz(bu_val(i, 2 * cp)));
            uint16_t h1 = f32_to_bf16(to_f32_ftz(bu_val(i, 2 * cp + 1)));
            t.v[i * 16 + cp] = (uint32_t)h0 | ((uint32_t)h1 << 16);
        }
    return t;
}
static constexpr ATbl make_aL() {
    ATbl t{};
    for (int i = 0; i < NS; ++i)
        for (int cp = 0; cp < 16; ++cp) {
            float f0 = to_f32_ftz(bu_val(i, 2 * cp));
            float f1 = to_f32_ftz(bu_val(i, 2 * cp + 1));
            uint16_t l0 = f32_to_bf16(f0 - bf16_to_f32(f32_to_bf16(f0)));
            uint16_t l1 = f32_to_bf16(f1 - bf16_to_f32(f32_to_bf16(f1)));
            t.v[i * 16 + cp] = (uint32_t)l0 | ((uint32_t)l1 << 16);
        }
    return t;
}
static constexpr ATbl H_AH = make_aH();
static constexpr ATbl H_AL = make_aL();
__device__ ATbl g_aH = H_AH;
__device__ ATbl g_aL = H_AL;

// ---- helpers ----
__device__ __forceinline__ uint32_t smem_u32(const void* p) {
    uint32_t a;
    asm("{ .reg .u64 t; cvta.to.shared.u64 t, %1; cvt.u32.u64 %0, t; }" : "=r"(a) : "l"(p));
    return a;
}
__device__ __forceinline__ void mma16816(float* c, const uint32_t* a, const uint32_t* b) {
    asm volatile("mma.sync.aligned.m16n8k16.row.col.f32.bf16.bf16.f32 "
                 "{%0,%1,%2,%3}, {%4,%5,%6,%7}, {%8,%9}, {%0,%1,%2,%3};"
                 : "+f"(c[0]), "+f"(c[1]), "+f"(c[2]), "+f"(c[3])
                 : "r"(a[0]), "r"(a[1]), "r"(a[2]), "r"(a[3]), "r"(b[0]), "r"(b[1]));
}
__device__ __forceinline__ void ldsm_x4(uint32_t* b, uint32_t addr) {
    asm volatile("ldmatrix.sync.aligned.m8n8.x4.shared.b16 {%0,%1,%2,%3}, [%4];"
                 : "=r"(b[0]), "=r"(b[1]), "=r"(b[2]), "=r"(b[3]) : "r"(addr));
}
__device__ __forceinline__ uint32_t split_pack(float x, float y, uint32_t& lo) {
    __nv_bfloat162 H = __floats2bfloat162_rn(x, y);
    __nv_bfloat162 L = __floats2bfloat162_rn(x - __bfloat162float(H.x),
                                             y - __bfloat162float(H.y));
    lo = *(uint32_t*)&L;
    return *(uint32_t*)&H;
}

// ---- kernel: CTA = (bc, j-half), 256 threads (8 warps), 3 CTAs/SM ----
extern "C" __global__ void __launch_bounds__(256, 3)
bezier_hmma_kernel(const float* __restrict__ K, float* __restrict__ out) {
    __shared__ uint32_t sBH[JH * BSTRIDE_U32];  // Tt high  [j][p-pair]
    __shared__ uint32_t sBL[JH * BSTRIDE_U32];  // Tt low
    __shared__ uint32_t sKH[NP * BSTRIDE_U32];  // K  high  [p][q-pair]
    __shared__ uint32_t sKL[NP * BSTRIDE_U32];  // K  low

    const int tid  = threadIdx.x;
    const int w    = tid >> 5;
    const int l    = tid & 31;
    const int bc   = blockIdx.x >> 1;
    const int half = blockIdx.x & 1;
    const int c0   = l & 3;
    const uint32_t lane_off = (uint32_t)(l & 7) * 80u + (uint32_t)(l >> 3) * 16u;

    // ---- K: fp32 load, bf16 H/L split into q-contiguous rows (no transpose) ----
    {
        const float4* K4 = (const float4*)(K + (size_t)bc * (NP * NP));
        float4 kv = K4[tid];
        int p = tid >> 3, qp = (tid & 7) << 1;       // q-pair index
        uint32_t h0, h1, l0, l1;
        h0 = split_pack(kv.x, kv.y, l0);
        h1 = split_pack(kv.z, kv.w, l1);
        *(uint2*)(sKH + p * BSTRIDE_U32 + qp) = make_uint2(h0, h1);
        *(uint2*)(sKL + p * BSTRIDE_U32 + qp) = make_uint2(l0, l1);
    }
    __syncthreads();

    // ---- stage 1 (HMMA): Tt[j,p] = sum_q bv[j,q] * K[p,q]; warp = 16 j-rows ----
    {
        const int jg = half * JH + w * 16 + (l >> 2);     // global j for A-frag rows
        uint32_t avH[2][4], avL[2][4];
#pragma unroll
        for (int ks = 0; ks < 2; ++ks) {
            int ra = jg * 16, rb = (jg + 8) * 16;
            int ca = c0 + 8 * ks, cb = c0 + 4 + 8 * ks;
            avH[ks][0] = __ldg(&g_aH.v[ra + ca]);
            avH[ks][1] = __ldg(&g_aH.v[rb + ca]);
            avH[ks][2] = __ldg(&g_aH.v[ra + cb]);
            avH[ks][3] = __ldg(&g_aH.v[rb + cb]);
            avL[ks][0] = __ldg(&g_aL.v[ra + ca]);
            avL[ks][1] = __ldg(&g_aL.v[rb + ca]);
            avL[ks][2] = __ldg(&g_aL.v[ra + cb]);
            avL[ks][3] = __ldg(&g_aL.v[rb + cb]);
        }

        const uint32_t kHb = smem_u32(sKH) + lane_off;
        const uint32_t kLb = smem_u32(sKL) + lane_off;
        const int jl = w * 16 + (l >> 2);
#pragma unroll
        for (int nt = 0; nt < 4; ++nt) {                  // p-groups of 8
            uint32_t kH[4], kL[4];
            ldsm_x4(kH, kHb + (uint32_t)nt * 640u);
            ldsm_x4(kL, kLb + (uint32_t)nt * 640u);
            float ct[4] = {0.f, 0.f, 0.f, 0.f};
            mma16816(ct, avH[0], &kH[0]);
            mma16816(ct, avH[1], &kH[2]);
            mma16816(ct, avH[0], &kL[0]);
            mma16816(ct, avH[1], &kL[2]);
            mma16816(ct, avL[0], &kH[0]);
            mma16816(ct, avL[1], &kH[2]);
            // (c0,c1) = (jl, p), (jl, p+1); (c2,c3) = (jl+8, ...)
            uint32_t lo, hi;
            hi = split_pack(ct[0], ct[1], lo);
            sBH[jl * BSTRIDE_U32 + nt * 4 + c0] = hi;
            sBL[jl * BSTRIDE_U32 + nt * 4 + c0] = lo;
            hi = split_pack(ct[2], ct[3], lo);
            sBH[(jl + 8) * BSTRIDE_U32 + nt * 4 + c0] = hi;
            sBL[(jl + 8) * BSTRIDE_U32 + nt * 4 + c0] = lo;
        }
    }

    // ---- stage-2 A fragments (bu rows w*32..+31, all 32 p) ----
    uint32_t AH[2][2][4], AL[2][2][4];
    {
        const int r0 = w * 32 + (l >> 2);
#pragma unroll
        for (int mt = 0; mt < 2; ++mt)
#pragma unroll
            for (int ks = 0; ks < 2; ++ks) {
                int ra = (r0 + 16 * mt) * 16, rb = (r0 + 8 + 16 * mt) * 16;
                int ca = c0 + 8 * ks, cb = c0 + 4 + 8 * ks;
                AH[mt][ks][0] = __ldg(&g_aH.v[ra + ca]);
                AH[mt][ks][1] = __ldg(&g_aH.v[rb + ca]);
                AH[mt][ks][2] = __ldg(&g_aH.v[ra + cb]);
                AH[mt][ks][3] = __ldg(&g_aH.v[rb + cb]);
                AL[mt][ks][0] = __ldg(&g_aL.v[ra + ca]);
                AL[mt][ks][1] = __ldg(&g_aL.v[rb + ca]);
                AL[mt][ks][2] = __ldg(&g_aL.v[ra + cb]);
                AL[mt][ks][3] = __ldg(&g_aL.v[rb + cb]);
            }
    }
    __syncthreads();

    // ---- stage 2 (HMMA): out rows w*32..+31, 8 chunks of 16 local cols ----
    const uint32_t bHbase = smem_u32(sBH) + lane_off;
    const uint32_t bLbase = smem_u32(sBL) + lane_off;
    float* outb = out + ((size_t)bc << 16) + half * JH;

#pragma unroll 1
    for (int jb = 0; jb < 8; ++jb) {
        uint32_t bH[2][4], bL[2][4];
#pragma unroll
        for (int nt = 0; nt < 2; ++nt) {
            uint32_t off = (uint32_t)(jb * 16 + nt * 8) * 80u;
            ldsm_x4(bH[nt], bHbase + off);
            ldsm_x4(bL[nt], bLbase + off);
        }

        float c[2][2][4];
#pragma unroll
        for (int mt = 0; mt < 2; ++mt)
#pragma unroll
            for (int nt = 0; nt < 2; ++nt)
#pragma unroll
                for (int g = 0; g < 4; ++g) c[mt][nt][g] = 0.0f;

        // term-major: 4 independent chains between RAW-dependent MMAs
#pragma unroll
        for (int term = 0; term < 6; ++term) {
            const uint32_t* a0 = (term < 4) ? AH[0][term & 1] : AL[0][term & 1];
            const uint32_t* a1 = (term < 4) ? AH[1][term & 1] : AL[1][term & 1];
            const int useL = (term == 2 || term == 3);
#pragma unroll
            for (int nt = 0; nt < 2; ++nt) {
                const uint32_t* bb = useL ? &bL[nt][(term & 1) * 2]
                                          : &bH[nt][(term & 1) * 2];
                mma16816(c[0][nt], a0, bb);
                mma16816(c[1][nt], a1, bb);
            }
        }

#pragma unroll
        for (int mt = 0; mt < 2; ++mt)
#pragma unroll
            for (int nt = 0; nt < 2; ++nt) {
                int row = w * 32 + mt * 16 + (l >> 2);
                int col = jb * 16 + nt * 8 + 2 * c0;
                __stcs((float2*)(outb + (size_t)row * NS + col),
                       make_float2(c[mt][nt][0], c[mt][nt][1]));
                __stcs((float2*)(outb + (size_t)(row + 8) * NS + col),
                       make_float2(c[mt][nt][2], c[mt][nt][3]));
            }
    }
}

extern "C" void kernel_launch(void* const* d_in, const int* in_sizes, int n_in,
                              void* d_out, int out_size) {
    const float* K = nullptr;
    for (int i = 0; i < n_in; ++i)
        if (in_sizes[i] == NBC * NP * NP) K = (const float*)d_in[i];
    if (!K) K = (const float*)d_in[n_in - 1];

    bezier_hmma_kernel<<<NBC * 2, 256>>>(K, (float*)d_out);
}

// round 13
// speedup vs baseline: 1.1453x; 1.1453x over previous
#include <cuda_runtime.h>
#include <cuda_bf16.h>
#include <cstdint>

// BezierSurfaceFitter, all-HMMA + butterfly-coalesced epilogue (STG.128).
// CTA = (bc, j-half), grid 1536, 8 warps.
// bf16 H/L split everywhere: X·Y ≈ XH·YH + XH·YL + XL·YH (~2^-18 term dropped).

#define NS  256
#define NP  32
#define NBC 768
#define BSTRIDE_U32 20   // 80-byte row stride (bf16x2 words) for ldsm tiles
#define JH  128          // j columns per CTA

// ---- compile-time Bernstein basis ----
static constexpr float to_f32_ftz(double x) {
    return (x < 1.1754943508222875e-38 && x > -1.1754943508222875e-38)
               ? 0.0f : (float)x;
}
static constexpr uint16_t f32_to_bf16(float f) {
    if (f == 0.0f) return 0;
    uint32_t u = __builtin_bit_cast(uint32_t, f);
    return (uint16_t)((u + 0x7FFFu + ((u >> 16) & 1u)) >> 16);
}
static constexpr float bf16_to_f32(uint16_t h) {
    return __builtin_bit_cast(float, (uint32_t)h << 16);
}
static constexpr double bu_val(int i, int p) {
    double tt = ((double)i + 0.5) / NS, u = 1.0 - tt;
    double c = 1.0;
    for (int k = 0; k < p; ++k) c = c * (double)(NP - 1 - k) / (double)(k + 1);
    double tp = 1.0; for (int k = 0; k < p; ++k) tp *= tt;
    double up = 1.0; for (int k = 0; k < NP - 1 - p; ++k) up *= u;
    return c * tp * up;
}
// bf16-pair tables in mma-A-fragment addressing: v[i*16+cp] = (bu[i][2cp], bu[i][2cp+1])
struct ATbl { uint32_t v[NS * 16]; };
static constexpr ATbl make_aH() {
    ATbl t{};
    for (int i = 0; i < NS; ++i)
        for (int cp = 0; cp < 16; ++cp) {
            uint16_t h0 = f32_to_bf16(to_f32_ftz(bu_val(i, 2 * cp)));
            uint16_t h1 = f32_to_bf16(to_f32_ftz(bu_val(i, 2 * cp + 1)));
            t.v[i * 16 + cp] = (uint32_t)h0 | ((uint32_t)h1 << 16);
        }
    return t;
}
static constexpr ATbl make_aL() {
    ATbl t{};
    for (int i = 0; i < NS; ++i)
        for (int cp = 0; cp < 16; ++cp) {
            float f0 = to_f32_ftz(bu_val(i, 2 * cp));
            float f1 = to_f32_ftz(bu_val(i, 2 * cp + 1));
            uint16_t l0 = f32_to_bf16(f0 - bf16_to_f32(f32_to_bf16(f0)));
            uint16_t l1 = f32_to_bf16(f1 - bf16_to_f32(f32_to_bf16(f1)));
            t.v[i * 16 + cp] = (uint32_t)l0 | ((uint32_t)l1 << 16);
        }
    return t;
}
static constexpr ATbl H_AH = make_aH();
static constexpr ATbl H_AL = make_aL();
__device__ ATbl g_aH = H_AH;
__device__ ATbl g_aL = H_AL;

// ---- helpers ----
__device__ __forceinline__ uint32_t smem_u32(const void* p) {
    uint32_t a;
    asm("{ .reg .u64 t; cvta.to.shared.u64 t, %1; cvt.u32.u64 %0, t; }" : "=r"(a) : "l"(p));
    return a;
}
__device__ __forceinline__ void mma16816(float* c, const uint32_t* a, const uint32_t* b) {
    asm volatile("mma.sync.aligned.m16n8k16.row.col.f32.bf16.bf16.f32 "
                 "{%0,%1,%2,%3}, {%4,%5,%6,%7}, {%8,%9}, {%0,%1,%2,%3};"
                 : "+f"(c[0]), "+f"(c[1]), "+f"(c[2]), "+f"(c[3])
                 : "r"(a[0]), "r"(a[1]), "r"(a[2]), "r"(a[3]), "r"(b[0]), "r"(b[1]));
}
__device__ __forceinline__ void ldsm_x4(uint32_t* b, uint32_t addr) {
    asm volatile("ldmatrix.sync.aligned.m8n8.x4.shared.b16 {%0,%1,%2,%3}, [%4];"
                 : "=r"(b[0]), "=r"(b[1]), "=r"(b[2]), "=r"(b[3]) : "r"(addr));
}
__device__ __forceinline__ uint32_t split_pack(float x, float y, uint32_t& lo) {
    __nv_bfloat162 H = __floats2bfloat162_rn(x, y);
    __nv_bfloat162 L = __floats2bfloat162_rn(x - __bfloat162float(H.x),
                                             y - __bfloat162float(H.y));
    lo = *(uint32_t*)&L;
    return *(uint32_t*)&H;
}

// ---- kernel: CTA = (bc, j-half), 256 threads (8 warps), 3 CTAs/SM ----
extern "C" __global__ void __launch_bounds__(256, 3)
bezier_hmma_kernel(const float* __restrict__ K, float* __restrict__ out) {
    __shared__ uint32_t sBH[JH * BSTRIDE_U32];  // Tt high  [j][p-pair]
    __shared__ uint32_t sBL[JH * BSTRIDE_U32];  // Tt low
    __shared__ uint32_t sKH[NP * BSTRIDE_U32];  // K  high  [p][q-pair]
    __shared__ uint32_t sKL[NP * BSTRIDE_U32];  // K  low

    const int tid  = threadIdx.x;
    const int w    = tid >> 5;
    const int l    = tid & 31;
    const int bc   = blockIdx.x >> 1;
    const int half = blockIdx.x & 1;
    const int c0   = l & 3;
    const uint32_t lane_off = (uint32_t)(l & 7) * 80u + (uint32_t)(l >> 3) * 16u;

    // ---- K: fp32 load, bf16 H/L split into q-contiguous rows (no transpose) ----
    {
        const float4* K4 = (const float4*)(K + (size_t)bc * (NP * NP));
        float4 kv = K4[tid];
        int p = tid >> 3, qp = (tid & 7) << 1;       // q-pair index
        uint32_t h0, h1, l0, l1;
        h0 = split_pack(kv.x, kv.y, l0);
        h1 = split_pack(kv.z, kv.w, l1);
        *(uint2*)(sKH + p * BSTRIDE_U32 + qp) = make_uint2(h0, h1);
        *(uint2*)(sKL + p * BSTRIDE_U32 + qp) = make_uint2(l0, l1);
    }
    __syncthreads();

    // ---- stage 1 (HMMA): Tt[j,p] = sum_q bv[j,q] * K[p,q]; warp = 16 j-rows ----
    {
        const int jg = half * JH + w * 16 + (l >> 2);     // global j for A-frag rows
        uint32_t avH[2][4], avL[2][4];
#pragma unroll
        for (int ks = 0; ks < 2; ++ks) {
            int ra = jg * 16, rb = (jg + 8) * 16;
            int ca = c0 + 8 * ks, cb = c0 + 4 + 8 * ks;
            avH[ks][0] = __ldg(&g_aH.v[ra + ca]);
            avH[ks][1] = __ldg(&g_aH.v[rb + ca]);
            avH[ks][2] = __ldg(&g_aH.v[ra + cb]);
            avH[ks][3] = __ldg(&g_aH.v[rb + cb]);
            avL[ks][0] = __ldg(&g_aL.v[ra + ca]);
            avL[ks][1] = __ldg(&g_aL.v[rb + ca]);
            avL[ks][2] = __ldg(&g_aL.v[ra + cb]);
            avL[ks][3] = __ldg(&g_aL.v[rb + cb]);
        }

        const uint32_t kHb = smem_u32(sKH) + lane_off;
        const uint32_t kLb = smem_u32(sKL) + lane_off;
        const int jl = w * 16 + (l >> 2);
#pragma unroll
        for (int nt = 0; nt < 4; ++nt) {                  // p-groups of 8
            uint32_t kH[4], kL[4];
            ldsm_x4(kH, kHb + (uint32_t)nt * 640u);
            ldsm_x4(kL, kLb + (uint32_t)nt * 640u);
            float ct[4] = {0.f, 0.f, 0.f, 0.f};
            mma16816(ct, avH[0], &kH[0]);
            mma16816(ct, avH[1], &kH[2]);
            mma16816(ct, avH[0], &kL[0]);
            mma16816(ct, avH[1], &kL[2]);
            mma16816(ct, avL[0], &kH[0]);
            mma16816(ct, avL[1], &kH[2]);
            uint32_t lo, hi;
            hi = split_pack(ct[0], ct[1], lo);
            sBH[jl * BSTRIDE_U32 + nt * 4 + c0] = hi;
            sBL[jl * BSTRIDE_U32 + nt * 4 + c0] = lo;
            hi = split_pack(ct[2], ct[3], lo);
            sBH[(jl + 8) * BSTRIDE_U32 + nt * 4 + c0] = hi;
            sBL[(jl + 8) * BSTRIDE_U32 + nt * 4 + c0] = lo;
        }
    }

    // ---- stage-2 A fragments (bu rows w*32..+31, all 32 p) ----
    uint32_t AH[2][2][4], AL[2][2][4];
    {
        const int r0 = w * 32 + (l >> 2);
#pragma unroll
        for (int mt = 0; mt < 2; ++mt)
#pragma unroll
            for (int ks = 0; ks < 2; ++ks) {
                int ra = (r0 + 16 * mt) * 16, rb = (r0 + 8 + 16 * mt) * 16;
                int ca = c0 + 8 * ks, cb = c0 + 4 + 8 * ks;
                AH[mt][ks][0] = __ldg(&g_aH.v[ra + ca]);
                AH[mt][ks][1] = __ldg(&g_aH.v[rb + ca]);
                AH[mt][ks][2] = __ldg(&g_aH.v[ra + cb]);
                AH[mt][ks][3] = __ldg(&g_aH.v[rb + cb]);
                AL[mt][ks][0] = __ldg(&g_aL.v[ra + ca]);
                AL[mt][ks][1] = __ldg(&g_aL.v[rb + ca]);
                AL[mt][ks][2] = __ldg(&g_aL.v[ra + cb]);
                AL[mt][ks][3] = __ldg(&g_aL.v[rb + cb]);
            }
    }
    __syncthreads();

    // ---- stage 2 (HMMA): out rows w*32..+31, 8 chunks of 16 local cols ----
    const uint32_t bHbase = smem_u32(sBH) + lane_off;
    const uint32_t bLbase = smem_u32(sBL) + lane_off;
    float* outb = out + ((size_t)bc << 16) + half * JH;
    const int odd = l & 1;

#pragma unroll 1
    for (int jb = 0; jb < 8; ++jb) {
        uint32_t bH[2][4], bL[2][4];
#pragma unroll
        for (int nt = 0; nt < 2; ++nt) {
            uint32_t off = (uint32_t)(jb * 16 + nt * 8) * 80u;
            ldsm_x4(bH[nt], bHbase + off);
            ldsm_x4(bL[nt], bLbase + off);
        }

        float c[2][2][4];
#pragma unroll
        for (int mt = 0; mt < 2; ++mt)
#pragma unroll
            for (int nt = 0; nt < 2; ++nt)
#pragma unroll
                for (int g = 0; g < 4; ++g) c[mt][nt][g] = 0.0f;

        // term-major: independent chains between RAW-dependent MMAs
#pragma unroll
        for (int term = 0; term < 6; ++term) {
            const uint32_t* a0 = (term < 4) ? AH[0][term & 1] : AL[0][term & 1];
            const uint32_t* a1 = (term < 4) ? AH[1][term & 1] : AL[1][term & 1];
            const int useL = (term == 2 || term == 3);
#pragma unroll
            for (int nt = 0; nt < 2; ++nt) {
                const uint32_t* bb = useL ? &bL[nt][(term & 1) * 2]
                                          : &bH[nt][(term & 1) * 2];
                mma16816(c[0][nt], a0, bb);
                mma16816(c[1][nt], a1, bb);
            }
        }

        // butterfly epilogue: lane l<->l^1 exchange one nt-pair -> contiguous float4
        // even lane: cols 4a..4a+3 of nt0 block; odd: cols 8+4a..+3 of nt1 (a=c0>>1)
        const int colbase = jb * 16 + (odd << 3) + ((c0 >> 1) << 2);
#pragma unroll
        for (int mt = 0; mt < 2; ++mt)
#pragma unroll
            for (int h = 0; h < 2; ++h) {
                float sx = odd ? c[mt][0][2 * h]     : c[mt][1][2 * h];
                float sy = odd ? c[mt][0][2 * h + 1] : c[mt][1][2 * h + 1];
                float rx = __shfl_xor_sync(0xffffffffu, sx, 1);
                float ry = __shfl_xor_sync(0xffffffffu, sy, 1);
                float4 v = odd
                    ? make_float4(rx, ry, c[mt][1][2 * h], c[mt][1][2 * h + 1])
                    : make_float4(c[mt][0][2 * h], c[mt][0][2 * h + 1], rx, ry);
                int row = w * 32 + mt * 16 + h * 8 + (l >> 2);
                __stcs((float4*)(outb + (size_t)row * NS + colbase), v);
            }
    }
}

extern "C" void kernel_launch(void* const* d_in, const int* in_sizes, int n_in,
                              void* d_out, int out_size) {
    const float* K = nullptr;
    for (int i = 0; i < n_in; ++i)
        if (in_sizes[i] == NBC * NP * NP) K = (const float*)d_in[i];
    if (!K) K = (const float*)d_in[n_in - 1];

    bezier_hmma_kernel<<<NBC * 2, 256>>>(K, (float*)d_out);
}